// round 9
// baseline (speedup 1.0000x reference)
#include <cuda_runtime.h>
#include <cstdint>

// Problem constants (from reference: B, S, D = 16, 4096, 512)
#define BB 16
#define SS 4096
#define DD 512
#define GRID_FUSED 1184       // 148 SMs x 8 blocks (single co-resident wave)
#define SEGS 4                // scan segments per batch
#define SEGLEN (SS / SEGS)    // 1024 elements per segment
#define NSCAN (BB * SEGS)     // 64 scan-participating blocks

// Scratch + sync state (zero at module load; reset in epilogue every launch).
__device__ int g_src[BB * SS];
__device__ int g_counts[BB];
__device__ int g_segcnt[BB][SEGS];
__device__ int g_segoff[BB][SEGS];
__device__ int g_seg_arrived[BB];
__device__ int g_off_ready[BB];
__device__ int g_scan_done;
__device__ int g_all_ready;
__device__ int g_exit;

static __device__ __forceinline__ int ld_acquire(const int* p) {
    int v;
    asm volatile("ld.acquire.gpu.b32 %0, [%1];" : "=r"(v) : "l"(p) : "memory");
    return v;
}
static __device__ __forceinline__ void st_release(int* p, int v) {
    asm volatile("st.release.gpu.b32 [%0], %1;" :: "l"(p), "r"(v) : "memory");
}

// ---------------------------------------------------------------------------
// Fused kernel, distributed scan.
// Blocks 0..63: batch b = blk>>2, segment seg = blk&3 (1024 elems each).
//   1) block-local scan of keep flags (4/thread via float4)
//   2) publish segment count; last arriver per batch computes 4-seg prefix,
//      batch count, releases g_off_ready[b]
//   3) segment blocks write stable global ranks into g_src; seg 0 also
//      writes the mask row; publish via g_scan_done -> g_all_ready
// All 1184 blocks then run the persistent gather (R4 body, LTS-cap bound).
// Epilogue: last exiting block zeroes all sync state for the next replay.
// ---------------------------------------------------------------------------
__global__ void __launch_bounds__(256, 8)
fused_kernel(const float* __restrict__ x,
             const float4* __restrict__ probs4,
             const float4* __restrict__ uniform4,
             float* __restrict__ out_padded,
             float* __restrict__ out_mask,
             int max_length, int total_rows) {
    const int t = threadIdx.x;
    __shared__ int s_counts[BB];

    if (blockIdx.x < NSCAN) {
        const int b   = blockIdx.x >> 2;
        const int seg = blockIdx.x & 3;

        // ---- 1) local scan: 256 threads x 4 elements (one float4 each) ----
        const int idx4 = b * (SS / 4) + seg * (SEGLEN / 4) + t;
        float4 p = probs4[idx4];
        float4 u = uniform4[idx4];

        int keep[4];
        keep[0] = (u.x >= p.x) ? 1 : 0;
        keep[1] = (u.y >= p.y) ? 1 : 0;
        keep[2] = (u.z >= p.z) ? 1 : 0;
        keep[3] = (u.w >= p.w) ? 1 : 0;
        int local = keep[0] + keep[1] + keep[2] + keep[3];

        const int lane = t & 31;
        const int warp = t >> 5;
        int v = local;
#pragma unroll
        for (int o = 1; o < 32; o <<= 1) {
            int uu = __shfl_up_sync(0xffffffffu, v, o);
            if (lane >= o) v += uu;
        }
        __shared__ int warp_sums[8];
        if (lane == 31) warp_sums[warp] = v;
        __syncthreads();
        if (warp == 0 && lane < 8) {
            int w = warp_sums[lane];
#pragma unroll
            for (int o = 1; o < 8; o <<= 1) {
                int uu = __shfl_up_sync(0x000000ffu, w, o);
                if (lane >= o) w += uu;
            }
            warp_sums[lane] = w;
        }
        __syncthreads();
        const int seg_total = warp_sums[7];
        const int excl = v - local + (warp > 0 ? warp_sums[warp - 1] : 0);

        // ---- 2) publish segment count; last arriver builds batch prefix ----
        if (t == 0) {
            g_segcnt[b][seg] = seg_total;
            __threadfence();
            int old = atomicAdd(&g_seg_arrived[b], 1);
            if (old == SEGS - 1) {
                __threadfence();
                int c0 = g_segcnt[b][0];
                int c1 = g_segcnt[b][1];
                int c2 = g_segcnt[b][2];
                int c3 = g_segcnt[b][3];
                g_segoff[b][0] = 0;
                g_segoff[b][1] = c0;
                g_segoff[b][2] = c0 + c1;
                g_segoff[b][3] = c0 + c1 + c2;
                g_counts[b] = c0 + c1 + c2 + c3;
                __threadfence();
                st_release(&g_off_ready[b], 1);
            }
        }

        // ---- wait for this batch's offsets ----
        if (t == 0) {
            while (ld_acquire(&g_off_ready[b]) == 0) __nanosleep(128);
        }
        __syncthreads();

        // ---- 3) write stable global ranks; seg 0 writes mask row ----
        const int base_elem = seg * SEGLEN + t * 4;
        int r = g_segoff[b][seg] + excl;
#pragma unroll
        for (int i = 0; i < 4; i++) {
            if (keep[i]) {
                g_src[b * SS + r] = base_elem + i;
                r++;
            }
        }

        if (seg == 0) {
            const int count = g_counts[b];
            float* mrow = out_mask + (long long)b * max_length;
            for (int j = t; j < max_length; j += 256) {
                mrow[j] = (j < count) ? 1.0f : 0.0f;
            }
        }

        __syncthreads();
        if (t == 0) {
            __threadfence();
            int old = atomicAdd(&g_scan_done, 1);
            if (old == NSCAN - 1) {
                st_release(&g_all_ready, 1);
            }
        }
    }

    // ---------------- global release: all scans published ----------------
    if (t == 0) {
        while (ld_acquire(&g_all_ready) == 0) __nanosleep(256);
    }
    __syncthreads();
    if (t < BB) s_counts[t] = g_counts[t];
    __syncthreads();

    // ---------------- persistent gather (R4 body, LTS-cap bound) ----------------
    const int lane = t & 31;
    const int gw   = blockIdx.x * 8 + (t >> 5);
    const int nw   = gridDim.x * 8;

    for (int row = gw; row < total_rows; row += nw) {
        const int b = row / max_length;
        const int j = row - b * max_length;

        float4* dst = reinterpret_cast<float4*>(out_padded + (long long)row * DD);

        if (j < s_counts[b]) {
            const int s = __ldg(&g_src[b * SS + j]);
            const float4* src = reinterpret_cast<const float4*>(
                x + ((long long)b * SS + s) * DD);
            float4 v0 = __ldcg(src + lane);
            float4 v1 = __ldcg(src + lane + 32);
            float4 v2 = __ldcg(src + lane + 64);
            float4 v3 = __ldcg(src + lane + 96);
            __stcs(dst + lane,      v0);
            __stcs(dst + lane + 32, v1);
            __stcs(dst + lane + 64, v2);
            __stcs(dst + lane + 96, v3);
        } else {
            const float4 z = make_float4(0.f, 0.f, 0.f, 0.f);
            __stcs(dst + lane,      z);
            __stcs(dst + lane + 32, z);
            __stcs(dst + lane + 64, z);
            __stcs(dst + lane + 96, z);
        }
    }

    // ---------------- epilogue: reset sync state for next replay ----------------
    __syncthreads();
    if (t == 0) {
        int old = atomicAdd(&g_exit, 1);
        if (old == (int)gridDim.x - 1) {
#pragma unroll
            for (int b = 0; b < BB; b++) {
                g_seg_arrived[b] = 0;
                g_off_ready[b] = 0;
            }
            g_scan_done = 0;
            g_all_ready = 0;
            g_exit = 0;
        }
    }
}

// ---------------------------------------------------------------------------
// Launch: out_size = B*ML*(D+1)  =>  ML = out_size / (B*(D+1))
// ---------------------------------------------------------------------------
extern "C" void kernel_launch(void* const* d_in, const int* in_sizes, int n_in,
                              void* d_out, int out_size) {
    const float* x       = (const float*)d_in[0];
    const float* probs   = (const float*)d_in[1];
    const float* uniform = (const float*)d_in[2];
    float* out = (float*)d_out;

    const int max_length = out_size / (BB * (DD + 1));
    float* out_mask = out + (long long)BB * max_length * DD;
    const int total_rows = BB * max_length;

    fused_kernel<<<GRID_FUSED, 256>>>(x, (const float4*)probs,
                                      (const float4*)uniform,
                                      out, out_mask, max_length, total_rows);
}

// round 10
// speedup vs baseline: 1.2455x; 1.2455x over previous
#include <cuda_runtime.h>

// Problem constants (from reference: B, S, D = 16, 4096, 512)
#define BB 16
#define SS 4096
#define DD 512
#define SEGS 4
#define SEGLEN (SS / SEGS)      // 1024 elements per segment
#define SEGLEN4 (SEGLEN / 4)    // 256 float4 per segment

// Scratch — per-batch compacted source indices + counts
__device__ int g_src[BB * SS];
__device__ int g_counts[BB];

// ---------------------------------------------------------------------------
// Kernel 1: segmented stable compaction scan, no inter-block communication.
// 64 blocks x 256 threads: block (b, seg) handles segment seg of batch b.
// Global offset of this segment = sum of keep-counts of segments < seg,
// computed by REDUNDANTLY loading+reducing those segments' flags (cheap:
// <=3KB extra loads per block). Own segment gets a block-wide exclusive
// scan -> stable packed ranks. Segment 3 also writes count + mask row.
// ---------------------------------------------------------------------------
__global__ void __launch_bounds__(256)
scan_kernel(const float4* __restrict__ probs4, const float4* __restrict__ uniform4,
            float* __restrict__ out_mask, int max_length) {
    const int b   = blockIdx.x >> 2;
    const int seg = blockIdx.x & 3;
    const int t   = threadIdx.x;
    const int lane = t & 31;
    const int warp = t >> 5;

    __shared__ int warp_red[8];
    __shared__ int warp_sums[8];

    const int batch4 = b * (SS / 4);

    // ---- 1) per-thread sum over preceding segments (redundant loads) ----
    int pre = 0;
    for (int q = 0; q < seg; q++) {
        float4 p = probs4[batch4 + q * SEGLEN4 + t];
        float4 u = uniform4[batch4 + q * SEGLEN4 + t];
        pre += (u.x >= p.x) + (u.y >= p.y) + (u.z >= p.z) + (u.w >= p.w);
    }

    // ---- 2) own segment flags ----
    float4 p = probs4[batch4 + seg * SEGLEN4 + t];
    float4 u = uniform4[batch4 + seg * SEGLEN4 + t];
    int keep[4];
    keep[0] = (u.x >= p.x) ? 1 : 0;
    keep[1] = (u.y >= p.y) ? 1 : 0;
    keep[2] = (u.z >= p.z) ? 1 : 0;
    keep[3] = (u.w >= p.w) ? 1 : 0;
    const int local = keep[0] + keep[1] + keep[2] + keep[3];

    // ---- 3) block reduce of 'pre' (offset of this segment) ----
    int rsum = pre;
#pragma unroll
    for (int o = 16; o > 0; o >>= 1)
        rsum += __shfl_down_sync(0xffffffffu, rsum, o);
    if (lane == 0) warp_red[warp] = rsum;

    // ---- 4) block inclusive scan of 'local' ----
    int v = local;
#pragma unroll
    for (int o = 1; o < 32; o <<= 1) {
        int uu = __shfl_up_sync(0xffffffffu, v, o);
        if (lane >= o) v += uu;
    }
    if (lane == 31) warp_sums[warp] = v;
    __syncthreads();
    if (warp == 0 && lane < 8) {
        // scan the 8 warp totals
        int w = warp_sums[lane];
#pragma unroll
        for (int o = 1; o < 8; o <<= 1) {
            int uu = __shfl_up_sync(0x000000ffu, w, o);
            if (lane >= o) w += uu;
        }
        warp_sums[lane] = w;
        // reduce the 8 warp 'pre' sums
        int rr = warp_red[lane];
#pragma unroll
        for (int o = 4; o > 0; o >>= 1)
            rr += __shfl_down_sync(0x000000ffu, rr, o);
        if (lane == 0) warp_red[0] = rr;
    }
    __syncthreads();

    const int seg_offset = warp_red[0];
    const int seg_total  = warp_sums[7];
    const int excl = v - local + (warp > 0 ? warp_sums[warp - 1] : 0);

    // ---- 5) write stable global ranks ----
    const int base_elem = seg * SEGLEN + t * 4;
    int r = seg_offset + excl;
#pragma unroll
    for (int i = 0; i < 4; i++) {
        if (keep[i]) {
            g_src[b * SS + r] = base_elem + i;
            r++;
        }
    }

    // ---- 6) segment 3 knows the full count: publish count + mask row ----
    if (seg == SEGS - 1) {
        const int count = seg_offset + seg_total;
        if (t == 0) g_counts[b] = count;
        float* mrow = out_mask + (long long)b * max_length;
        for (int j = t; j < max_length; j += 256) {
            mrow[j] = (j < count) ? 1.0f : 0.0f;
        }
    }
}

// ---------------------------------------------------------------------------
// Kernel 2: gather + pad (unchanged R4 body — sits on the LTS cap).
// Persistent grid, one row per warp per iteration, 4x LDG.128 front-batched.
// ---------------------------------------------------------------------------
__global__ void __launch_bounds__(256, 8)
gather_kernel(const float* __restrict__ x,
              float* __restrict__ out_padded,
              int max_length, int total_rows) {
    __shared__ int s_counts[BB];
    if (threadIdx.x < BB) s_counts[threadIdx.x] = g_counts[threadIdx.x];
    __syncthreads();

    const int lane = threadIdx.x & 31;
    const int gw   = blockIdx.x * 8 + (threadIdx.x >> 5);
    const int nw   = gridDim.x * 8;

    for (int row = gw; row < total_rows; row += nw) {
        const int b = row / max_length;
        const int j = row - b * max_length;

        float4* dst = reinterpret_cast<float4*>(out_padded + (long long)row * DD);

        if (j < s_counts[b]) {
            const int s = __ldg(&g_src[b * SS + j]);
            const float4* src = reinterpret_cast<const float4*>(
                x + ((long long)b * SS + s) * DD);
            float4 v0 = __ldcg(src + lane);
            float4 v1 = __ldcg(src + lane + 32);
            float4 v2 = __ldcg(src + lane + 64);
            float4 v3 = __ldcg(src + lane + 96);
            __stcs(dst + lane,      v0);
            __stcs(dst + lane + 32, v1);
            __stcs(dst + lane + 64, v2);
            __stcs(dst + lane + 96, v3);
        } else {
            const float4 z = make_float4(0.f, 0.f, 0.f, 0.f);
            __stcs(dst + lane,      z);
            __stcs(dst + lane + 32, z);
            __stcs(dst + lane + 64, z);
            __stcs(dst + lane + 96, z);
        }
    }
}

// ---------------------------------------------------------------------------
// Launch: out_size = B*ML*(D+1)  =>  ML = out_size / (B*(D+1))
// ---------------------------------------------------------------------------
extern "C" void kernel_launch(void* const* d_in, const int* in_sizes, int n_in,
                              void* d_out, int out_size) {
    const float* x       = (const float*)d_in[0];
    const float* probs   = (const float*)d_in[1];
    const float* uniform = (const float*)d_in[2];
    float* out = (float*)d_out;

    const int max_length = out_size / (BB * (DD + 1));
    float* out_mask = out + (long long)BB * max_length * DD;
    const int total_rows = BB * max_length;

    scan_kernel<<<BB * SEGS, 256>>>((const float4*)probs, (const float4*)uniform,
                                    out_mask, max_length);

    const int blocks = 1184;  // 148 SMs x 8 blocks (persistent single wave)
    gather_kernel<<<blocks, 256>>>(x, out, max_length, total_rows);
}

// round 11
// speedup vs baseline: 1.2473x; 1.0014x over previous
#include <cuda_runtime.h>

// Problem constants (from reference: B, S, D = 16, 4096, 512)
#define BB 16
#define SS 4096
#define DD 512

// Scratch — per-batch compacted source indices + counts
__device__ int g_src[BB * SS];
__device__ int g_counts[BB];

// ---------------------------------------------------------------------------
// Kernel 1: per-batch stable compaction index build + mask output.
// One block per batch, 1024 threads x 4 elements (float4 loads).
// Triggers programmatic launch completion as soon as g_src/g_counts are
// published, so the dependent gather grid starts launching while the mask
// rows are still being written.
// ---------------------------------------------------------------------------
__global__ void __launch_bounds__(1024)
scan_kernel(const float4* __restrict__ probs4, const float4* __restrict__ uniform4,
            float* __restrict__ out_mask, int max_length) {
    const int b = blockIdx.x;
    const int t = threadIdx.x;
    const int idx4 = b * (SS / 4) + t;

    float4 p = probs4[idx4];
    float4 u = uniform4[idx4];

    int keep[4];
    keep[0] = (u.x >= p.x) ? 1 : 0;
    keep[1] = (u.y >= p.y) ? 1 : 0;
    keep[2] = (u.z >= p.z) ? 1 : 0;
    keep[3] = (u.w >= p.w) ? 1 : 0;
    int local = keep[0] + keep[1] + keep[2] + keep[3];

    const int lane = t & 31;
    const int warp = t >> 5;
    int v = local;
#pragma unroll
    for (int o = 1; o < 32; o <<= 1) {
        int uu = __shfl_up_sync(0xffffffffu, v, o);
        if (lane >= o) v += uu;
    }
    __shared__ int warp_sums[32];
    __shared__ int s_total;
    if (lane == 31) warp_sums[warp] = v;
    __syncthreads();
    if (warp == 0) {
        int w = warp_sums[lane];
#pragma unroll
        for (int o = 1; o < 32; o <<= 1) {
            int uu = __shfl_up_sync(0xffffffffu, w, o);
            if (lane >= o) w += uu;
        }
        warp_sums[lane] = w;
        if (lane == 31) s_total = w;
    }
    __syncthreads();

    int excl = v - local + (warp > 0 ? warp_sums[warp - 1] : 0);

    int r = excl;
#pragma unroll
    for (int i = 0; i < 4; i++) {
        if (keep[i]) {
            g_src[b * SS + r] = t * 4 + i;
            r++;
        }
    }

    const int count = s_total;
    if (t == 0) g_counts[b] = count;

    // g_src/g_counts for this block are now written — allow the dependent
    // gather grid to begin launching. (Its blocks still block in
    // cudaGridDependencySynchronize() until this whole grid completes, which
    // guarantees visibility of all writes including the mask rows below.)
    cudaTriggerProgrammaticLaunchCompletion();

    // Mask row for this batch.
    float* mrow = out_mask + (long long)b * max_length;
    for (int j = t; j < max_length; j += 1024) {
        mrow[j] = (j < count) ? 1.0f : 0.0f;
    }
}

// ---------------------------------------------------------------------------
// Kernel 2: gather + pad (R4 body — sits on the LTS cap: ~136.5MB compulsory
// L2 traffic / ~6300 B/cyc ≈ 20.5us; structure beyond coalescing is moot).
// Persistent grid, one row per warp per iteration, 4x LDG.128 front-batched.
// PDL: blocks launch during the scan, then wait for scan-grid completion.
// ---------------------------------------------------------------------------
__global__ void __launch_bounds__(256, 8)
gather_kernel(const float* __restrict__ x,
              float* __restrict__ out_padded,
              int max_length, int total_rows) {
    // Wait for the preceding (scan) grid's completion + memory visibility.
    cudaGridDependencySynchronize();

    __shared__ int s_counts[BB];
    if (threadIdx.x < BB) s_counts[threadIdx.x] = g_counts[threadIdx.x];
    __syncthreads();

    const int lane = threadIdx.x & 31;
    const int gw   = blockIdx.x * 8 + (threadIdx.x >> 5);
    const int nw   = gridDim.x * 8;

    for (int row = gw; row < total_rows; row += nw) {
        const int b = row / max_length;
        const int j = row - b * max_length;

        float4* dst = reinterpret_cast<float4*>(out_padded + (long long)row * DD);

        if (j < s_counts[b]) {
            const int s = __ldg(&g_src[b * SS + j]);
            const float4* src = reinterpret_cast<const float4*>(
                x + ((long long)b * SS + s) * DD);
            float4 v0 = __ldcg(src + lane);
            float4 v1 = __ldcg(src + lane + 32);
            float4 v2 = __ldcg(src + lane + 64);
            float4 v3 = __ldcg(src + lane + 96);
            __stcs(dst + lane,      v0);
            __stcs(dst + lane + 32, v1);
            __stcs(dst + lane + 64, v2);
            __stcs(dst + lane + 96, v3);
        } else {
            const float4 z = make_float4(0.f, 0.f, 0.f, 0.f);
            __stcs(dst + lane,      z);
            __stcs(dst + lane + 32, z);
            __stcs(dst + lane + 64, z);
            __stcs(dst + lane + 96, z);
        }
    }
}

// ---------------------------------------------------------------------------
// Launch: out_size = B*ML*(D+1)  =>  ML = out_size / (B*(D+1))
// Gather is launched with Programmatic Stream Serialization so it overlaps
// with the scan's tail instead of paying a full end-of-kernel launch gap.
// ---------------------------------------------------------------------------
extern "C" void kernel_launch(void* const* d_in, const int* in_sizes, int n_in,
                              void* d_out, int out_size) {
    const float* x       = (const float*)d_in[0];
    const float* probs   = (const float*)d_in[1];
    const float* uniform = (const float*)d_in[2];
    float* out = (float*)d_out;

    const int max_length = out_size / (BB * (DD + 1));
    float* out_mask = out + (long long)BB * max_length * DD;
    const int total_rows = BB * max_length;

    scan_kernel<<<BB, 1024>>>((const float4*)probs, (const float4*)uniform,
                              out_mask, max_length);

    cudaLaunchConfig_t cfg = {};
    cfg.gridDim  = dim3(1184, 1, 1);   // 148 SMs x 8 blocks
    cfg.blockDim = dim3(256, 1, 1);
    cfg.dynamicSmemBytes = 0;
    cfg.stream = 0;
    cudaLaunchAttribute attr[1];
    attr[0].id = cudaLaunchAttributeProgrammaticStreamSerialization;
    attr[0].val.programmaticStreamSerializationAllowed = 1;
    cfg.attrs = attr;
    cfg.numAttrs = 1;
    cudaLaunchKernelEx(&cfg, gather_kernel, x, out, max_length, total_rows);
}